// round 11
// baseline (speedup 1.0000x reference)
#include <cuda_runtime.h>

#define B_N   4096
#define S_N   5
#define D_N   64
#define HS_N  961
#define VSA_N 1024
#define LN_EPSF 1e-3f
#define KPAD 72
#define KTOT 1096   // 8 * 137
#define MDIM 137

typedef unsigned long long ull;

__device__ float g_sp[S_N * VSA_N];               // batch-invariant sp rows
__device__ __align__(16) float g_hs[S_N * KTOT];  // prebuilt strided padded h (R2 layout)

// ---- packed f32x2 primitives (sm_103a) ----
#define PACK2(dst, lo, hi) \
    asm("mov.b64 %0, {%1, %2};" : "=l"(dst) : "f"(lo), "f"(hi))
#define FMA2(acc, a, b) \
    asm("fma.rn.f32x2 %0, %1, %2, %0;" : "+l"(acc) : "l"(a), "l"(b))
#define UNPACK2(lo, hi, src) \
    asm("mov.b64 {%0, %1}, %2;" : "=f"(lo), "=f"(hi) : "l"(src))

__device__ __forceinline__ float fast_silu(float x) {
    return x / (1.0f + __expf(-x));
}

// conv for 8 consecutive outputs t0..t0+7 (t0 = 8*tid).  [VERBATIM R2 - PROVEN]
__device__ __forceinline__ void conv_row2(const float* __restrict__ hsi,
                                          const float* __restrict__ xs,
                                          int t0, float acc[8]) {
    unsigned long long acc2[4] = {0ull, 0ull, 0ull, 0ull};
    unsigned long long pw[8];
    const float* hp = hsi + ((1032 - t0) >> 3);
    float lprev;
    {   // prime: l_{-7}..l_{-1}; packs pw_{-6}..pw_{-1} -> slots 2..7
        float lp[7];
        #pragma unroll
        for (int j = 0; j < 7; ++j) {
            const int d = j - 7;
            lp[j] = hp[(d & 7) * MDIM + (d >> 3)];
        }
        #pragma unroll
        for (int j = 1; j < 7; ++j) {
            const int d = j - 7;
            PACK2(pw[d & 7], lp[j - 1], lp[j]);
        }
        lprev = lp[6];
    }
    const float* hq = hp;
    #pragma unroll 2
    for (int c = 0; c < 8; ++c) {
        float ln[8];
        #pragma unroll
        for (int s = 0; s < 8; ++s) ln[s] = hq[s * MDIM];   // 8 independent LDS
        float4 xa = *reinterpret_cast<const float4*>(xs + (c << 3));
        float4 xb = *reinterpret_cast<const float4*>(xs + (c << 3) + 4);
        float xd[8] = {xa.x, xa.y, xa.z, xa.w, xb.x, xb.y, xb.z, xb.w};
        #pragma unroll
        for (int s = 0; s < 8; ++s) {
            float pv = (s == 0) ? lprev : ln[s - 1];
            PACK2(pw[s & 7], pv, ln[s]);                    // pw_d = (l_{d-1}, l_d)
            unsigned long long xx;
            PACK2(xx, xd[s], xd[s]);                        // (x_d, x_d)
            FMA2(acc2[0], xx, pw[s & 7]);                   // acc[1],acc[0]
            FMA2(acc2[1], xx, pw[(s + 6) & 7]);             // acc[3],acc[2]
            FMA2(acc2[2], xx, pw[(s + 4) & 7]);             // acc[5],acc[4]
            FMA2(acc2[3], xx, pw[(s + 2) & 7]);             // acc[7],acc[6]
        }
        lprev = ln[7];
        hq += 1;
    }
    #pragma unroll
    for (int p = 0; p < 4; ++p) UNPACK2(acc[2 * p + 1], acc[2 * p], acc2[p]);
}

// ---------------- kernel 0: build g_hs + sp rows (one block per i)  [R2 proven] ----------------
__global__ __launch_bounds__(128)
void sp_kernel(const float* __restrict__ h,
               const float* __restrict__ symbols,
               const float* __restrict__ gamma,
               const float* __restrict__ beta) {
    __shared__ __align__(16) float sh_hs[KTOT];
    __shared__ __align__(16) float sh_x[D_N];
    __shared__ float sh_red[8];
    __shared__ float sh_stats[2];

    const int tid  = threadIdx.x;
    const int lane = tid & 31;
    const int warp = tid >> 5;
    const int i    = blockIdx.x;

    for (int K = tid; K < KTOT; K += 128) {
        const int k = K - KPAD;
        const float v = (k >= 0 && k < HS_N) ? h[i * HS_N + k] : 0.f;
        const int a = (K & 7) * MDIM + (K >> 3);
        sh_hs[a] = v;
        g_hs[i * KTOT + a] = v;
    }
    if (tid < D_N) sh_x[tid] = symbols[i * D_N + tid];
    __syncthreads();

    const int t0 = tid << 3;
    float acc[8];
    conv_row2(sh_hs, sh_x, t0, acc);

    float y[8];
    float s1 = 0.f, s2 = 0.f;
    #pragma unroll
    for (int r = 0; r < 8; ++r) {
        float u = fast_silu(acc[r]);
        y[r] = u; s1 += u; s2 += u * u;
    }
    #pragma unroll
    for (int o = 16; o > 0; o >>= 1) {
        s1 += __shfl_xor_sync(0xffffffffu, s1, o);
        s2 += __shfl_xor_sync(0xffffffffu, s2, o);
    }
    if (lane == 0) { sh_red[warp] = s1; sh_red[4 + warp] = s2; }
    __syncthreads();
    if (tid == 0) {
        float a = sh_red[0] + sh_red[1] + sh_red[2] + sh_red[3];
        float q = sh_red[4] + sh_red[5] + sh_red[6] + sh_red[7];
        float mu = a * (1.f / VSA_N);
        float var = q * (1.f / VSA_N) - mu * mu;
        sh_stats[0] = mu;
        sh_stats[1] = rsqrtf(var + LN_EPSF);
    }
    __syncthreads();
    float mu = sh_stats[0], rs = sh_stats[1];
    #pragma unroll
    for (int r = 0; r < 8; ++r) {
        const int t = t0 + r;
        g_sp[i * VSA_N + t] = fmaf((y[r] - mu) * rs, gamma[t], beta[t]);
    }
}

// ---------------- main fused kernel: one block per batch element ----------------
__global__ __launch_bounds__(128, 6)
void fused_main(const float* __restrict__ values,
                const float* __restrict__ gamma,
                const float* __restrict__ beta,
                float* __restrict__ out) {
    __shared__ __align__(16) float sh_hs[S_N * KTOT];    // 21920 B (R2 layout)
    __shared__ __align__(16) float sh_x[S_N * D_N];      // 1280 B
    __shared__ float sh_red[8];
    __shared__ float sh_stats[2];
    __shared__ int   sh_negw[4 * 25];
    __shared__ float sh_w[25];

    const int tid  = threadIdx.x;
    const int lane = tid & 31;
    const int warp = tid >> 5;
    const int b    = blockIdx.x;
    const int t0   = tid << 3;

    // verbatim copy of prebuilt strided h (5480 floats = 1370 float4)  [R2 proven]
    {
        const float4* src = reinterpret_cast<const float4*>(g_hs);
        float4* dst = reinterpret_cast<float4*>(sh_hs);
        #pragma unroll 1
        for (int idx = tid; idx < (S_N * KTOT) / 4; idx += 128) dst[idx] = src[idx];
    }
    for (int idx = tid; idx < S_N * D_N; idx += 128)
        sh_x[idx] = values[b * (S_N * D_N) + idx];
    __syncthreads();

    // ---- conv + silu + LayerNorm per i -> vp in REGISTERS  [conv: R2; vp-reg: R6] ----
    float vp[S_N * 8];
    #pragma unroll 1
    for (int i = 0; i < S_N; ++i) {
        float acc[8];
        conv_row2(sh_hs + i * KTOT, sh_x + i * D_N, t0, acc);

        float y[8];
        float s1 = 0.f, s2 = 0.f;
        #pragma unroll
        for (int r = 0; r < 8; ++r) {
            float u = fast_silu(acc[r]);
            y[r] = u; s1 += u; s2 += u * u;
        }
        #pragma unroll
        for (int o = 16; o > 0; o >>= 1) {
            s1 += __shfl_xor_sync(0xffffffffu, s1, o);
            s2 += __shfl_xor_sync(0xffffffffu, s2, o);
        }
        if (lane == 0) { sh_red[warp] = s1; sh_red[4 + warp] = s2; }
        __syncthreads();
        if (tid == 0) {
            float a = sh_red[0] + sh_red[1] + sh_red[2] + sh_red[3];
            float q = sh_red[4] + sh_red[5] + sh_red[6] + sh_red[7];
            float mu = a * (1.f / VSA_N);
            float var = q * (1.f / VSA_N) - mu * mu;
            sh_stats[0] = mu;
            sh_stats[1] = rsqrtf(var + LN_EPSF);
        }
        __syncthreads();
        float mu = sh_stats[0], rs = sh_stats[1];

        float4 g0  = *reinterpret_cast<const float4*>(gamma + t0);
        float4 g1  = *reinterpret_cast<const float4*>(gamma + t0 + 4);
        float4 be0 = *reinterpret_cast<const float4*>(beta + t0);
        float4 be1 = *reinterpret_cast<const float4*>(beta + t0 + 4);
        float gg[8] = {g0.x, g0.y, g0.z, g0.w, g1.x, g1.y, g1.z, g1.w};
        float bb[8] = {be0.x, be0.y, be0.z, be0.w, be1.x, be1.y, be1.z, be1.w};
        #pragma unroll
        for (int r = 0; r < 8; ++r)
            vp[i * 8 + r] = fmaf((y[r] - mu) * rs, gg[r], bb[r]);
    }

    // ---- scores: negative-count via sign-bit XOR over this thread's t0..t0+7  [R6 proven] ----
    int neg[25];
    #pragma unroll
    for (int q = 0; q < 25; ++q) neg[q] = 0;
    #pragma unroll 1
    for (int j = 0; j < S_N; ++j) {
        float4 s0 = *reinterpret_cast<const float4*>(g_sp + j * VSA_N + t0);
        float4 s1 = *reinterpret_cast<const float4*>(g_sp + j * VSA_N + t0 + 4);
        float spj[8] = {s0.x, s0.y, s0.z, s0.w, s1.x, s1.y, s1.z, s1.w};
        #pragma unroll
        for (int i = 0; i < S_N; ++i) {
            int cnt = 0;
            #pragma unroll
            for (int r = 0; r < 8; ++r) {
                float v = vp[i * 8 + r];
                float c = v + spj[r];
                cnt += (int)(((unsigned)(__float_as_int(v) ^ __float_as_int(c))) >> 31);
            }
            neg[j * 5 + i] = cnt;
        }
    }
    #pragma unroll
    for (int q = 0; q < 25; ++q) neg[q] = __reduce_add_sync(0xffffffffu, neg[q]);
    if (lane == 0) {
        #pragma unroll
        for (int q = 0; q < 25; ++q) sh_negw[warp * 25 + q] = neg[q];
    }
    __syncthreads();
    if (tid < 25) {
        int tot = sh_negw[tid] + sh_negw[25 + tid] + sh_negw[50 + tid] + sh_negw[75 + tid];
        sh_w[tid] = (float)(VSA_N - 2 * tot) * (1.f / VSA_N);
    }
    __syncthreads();
    if (tid < 5) {   // softmax over i for row j = tid
        float s[5];
        #pragma unroll
        for (int i = 0; i < 5; ++i) s[i] = sh_w[tid * 5 + i];
        float m = s[0];
        #pragma unroll
        for (int i = 1; i < 5; ++i) m = fmaxf(m, s[i]);
        float e[5]; float sum = 0.f;
        #pragma unroll
        for (int i = 0; i < 5; ++i) { e[i] = __expf(s[i] - m); sum += e[i]; }
        float inv = 1.f / sum;
        #pragma unroll
        for (int i = 0; i < 5; ++i) sh_w[tid * 5 + i] = e[i] * inv;
    }
    __syncthreads();

    // ---- att + final silu + vectorized store  [R6 proven] ----
    float wloc[25];
    #pragma unroll
    for (int q = 0; q < 25; ++q) wloc[q] = sh_w[q];
    const int ob = b * (S_N * VSA_N);
    #pragma unroll 1
    for (int j = 0; j < S_N; ++j) {
        float4 s0 = *reinterpret_cast<const float4*>(g_sp + j * VSA_N + t0);
        float4 s1 = *reinterpret_cast<const float4*>(g_sp + j * VSA_N + t0 + 4);
        float spj[8] = {s0.x, s0.y, s0.z, s0.w, s1.x, s1.y, s1.z, s1.w};
        float o[8];
        #pragma unroll
        for (int r = 0; r < 8; ++r) {
            float a = 0.f;
            #pragma unroll
            for (int i = 0; i < 5; ++i) a = fmaf(wloc[j * 5 + i], vp[i * 8 + r], a);
            o[r] = fast_silu(a * spj[r]);
        }
        *reinterpret_cast<float4*>(out + ob + j * VSA_N + t0)     = make_float4(o[0], o[1], o[2], o[3]);
        *reinterpret_cast<float4*>(out + ob + j * VSA_N + t0 + 4) = make_float4(o[4], o[5], o[6], o[7]);
    }
}

extern "C" void kernel_launch(void* const* d_in, const int* in_sizes, int n_in,
                              void* d_out, int out_size) {
    (void)in_sizes; (void)n_in; (void)out_size;
    const float* values  = (const float*)d_in[0];
    const float* h       = (const float*)d_in[1];
    const float* symbols = (const float*)d_in[2];
    const float* gamma   = (const float*)d_in[3];
    const float* beta    = (const float*)d_in[4];
    float* out = (float*)d_out;

    sp_kernel<<<S_N, 128>>>(h, symbols, gamma, beta);
    fused_main<<<B_N, 128>>>(values, gamma, beta, out);
}

// round 12
// speedup vs baseline: 1.6680x; 1.6680x over previous
#include <cuda_runtime.h>

#define B_N   4096
#define S_N   5
#define D_N   64
#define HS_N  961
#define VSA_N 1024
#define LN_EPSF 1e-3f
#define KPAD 72
#define KTOT 1096   // 8 * 137
#define MDIM 137

#define GROUPS 4
#define TPB    512

// dynamic smem layout (bytes)
#define OFF_HS   0                      // float[5480]            = 21920
#define OFF_X    21920                  // float[4][320]          = 5120
#define OFF_VP   27040                  // float[4][5120]         = 81920
#define OFF_AUX  108960                 // 4 * 544
#define AUX_STRIDE 544
#define SMEM_DYN (OFF_AUX + GROUPS * AUX_STRIDE)   // 111136

typedef unsigned long long ull;

__device__ float g_sp[S_N * VSA_N];               // batch-invariant sp rows
__device__ __align__(16) float g_hs[S_N * KTOT];  // prebuilt strided padded h (R2 layout)

// ---- packed f32x2 primitives (sm_103a) ----
#define PACK2(dst, lo, hi) \
    asm("mov.b64 %0, {%1, %2};" : "=l"(dst) : "f"(lo), "f"(hi))
#define FMA2(acc, a, b) \
    asm("fma.rn.f32x2 %0, %1, %2, %0;" : "+l"(acc) : "l"(a), "l"(b))
#define UNPACK2(lo, hi, src) \
    asm("mov.b64 {%0, %1}, %2;" : "=f"(lo), "=f"(hi) : "l"(src))

// group barrier: 128 threads of group g, named barrier id g+1
#define GBAR() asm volatile("bar.sync %0, %1;" :: "r"(g + 1), "r"(128) : "memory")

__device__ __forceinline__ float fast_silu(float x) {
    return x / (1.0f + __expf(-x));
}

// conv for 8 consecutive outputs t0..t0+7 (t0 = 8*tid_in_group).  [VERBATIM R2 - PROVEN]
__device__ __forceinline__ void conv_row2(const float* __restrict__ hsi,
                                          const float* __restrict__ xs,
                                          int t0, float acc[8]) {
    unsigned long long acc2[4] = {0ull, 0ull, 0ull, 0ull};
    unsigned long long pw[8];
    const float* hp = hsi + ((1032 - t0) >> 3);
    float lprev;
    {   // prime: l_{-7}..l_{-1}; packs pw_{-6}..pw_{-1} -> slots 2..7
        float lp[7];
        #pragma unroll
        for (int j = 0; j < 7; ++j) {
            const int d = j - 7;
            lp[j] = hp[(d & 7) * MDIM + (d >> 3)];
        }
        #pragma unroll
        for (int j = 1; j < 7; ++j) {
            const int d = j - 7;
            PACK2(pw[d & 7], lp[j - 1], lp[j]);
        }
        lprev = lp[6];
    }
    const float* hq = hp;
    #pragma unroll 2
    for (int c = 0; c < 8; ++c) {
        float ln[8];
        #pragma unroll
        for (int s = 0; s < 8; ++s) ln[s] = hq[s * MDIM];   // 8 independent LDS
        float4 xa = *reinterpret_cast<const float4*>(xs + (c << 3));
        float4 xb = *reinterpret_cast<const float4*>(xs + (c << 3) + 4);
        float xd[8] = {xa.x, xa.y, xa.z, xa.w, xb.x, xb.y, xb.z, xb.w};
        #pragma unroll
        for (int s = 0; s < 8; ++s) {
            float pv = (s == 0) ? lprev : ln[s - 1];
            PACK2(pw[s & 7], pv, ln[s]);                    // pw_d = (l_{d-1}, l_d)
            unsigned long long xx;
            PACK2(xx, xd[s], xd[s]);                        // (x_d, x_d)
            FMA2(acc2[0], xx, pw[s & 7]);                   // acc[1],acc[0]
            FMA2(acc2[1], xx, pw[(s + 6) & 7]);             // acc[3],acc[2]
            FMA2(acc2[2], xx, pw[(s + 4) & 7]);             // acc[5],acc[4]
            FMA2(acc2[3], xx, pw[(s + 2) & 7]);             // acc[7],acc[6]
        }
        lprev = ln[7];
        hq += 1;
    }
    #pragma unroll
    for (int p = 0; p < 4; ++p) UNPACK2(acc[2 * p + 1], acc[2 * p], acc2[p]);
}

// ---------------- kernel 0: build g_hs + sp rows (one block per i)  [VERBATIM R2 - PROVEN] ----------------
__global__ __launch_bounds__(128)
void sp_kernel(const float* __restrict__ h,
               const float* __restrict__ symbols,
               const float* __restrict__ gamma,
               const float* __restrict__ beta) {
    __shared__ __align__(16) float sh_hs[KTOT];
    __shared__ __align__(16) float sh_x[D_N];
    __shared__ float sh_red[8];
    __shared__ float sh_stats[2];

    const int tid  = threadIdx.x;
    const int lane = tid & 31;
    const int warp = tid >> 5;
    const int i    = blockIdx.x;

    for (int K = tid; K < KTOT; K += 128) {
        const int k = K - KPAD;
        const float v = (k >= 0 && k < HS_N) ? h[i * HS_N + k] : 0.f;
        const int a = (K & 7) * MDIM + (K >> 3);
        sh_hs[a] = v;
        g_hs[i * KTOT + a] = v;
    }
    if (tid < D_N) sh_x[tid] = symbols[i * D_N + tid];
    __syncthreads();

    const int t0 = tid << 3;
    float acc[8];
    conv_row2(sh_hs, sh_x, t0, acc);

    float y[8];
    float s1 = 0.f, s2 = 0.f;
    #pragma unroll
    for (int r = 0; r < 8; ++r) {
        float u = fast_silu(acc[r]);
        y[r] = u; s1 += u; s2 += u * u;
    }
    #pragma unroll
    for (int o = 16; o > 0; o >>= 1) {
        s1 += __shfl_xor_sync(0xffffffffu, s1, o);
        s2 += __shfl_xor_sync(0xffffffffu, s2, o);
    }
    if (lane == 0) { sh_red[warp] = s1; sh_red[4 + warp] = s2; }
    __syncthreads();
    if (tid == 0) {
        float a = sh_red[0] + sh_red[1] + sh_red[2] + sh_red[3];
        float q = sh_red[4] + sh_red[5] + sh_red[6] + sh_red[7];
        float mu = a * (1.f / VSA_N);
        float var = q * (1.f / VSA_N) - mu * mu;
        sh_stats[0] = mu;
        sh_stats[1] = rsqrtf(var + LN_EPSF);
    }
    __syncthreads();
    float mu = sh_stats[0], rs = sh_stats[1];
    #pragma unroll
    for (int r = 0; r < 8; ++r) {
        const int t = t0 + r;
        g_sp[i * VSA_N + t] = fmaf((y[r] - mu) * rs, gamma[t], beta[t]);
    }
}

// ---------------- main fused kernel: 4 batch groups per 512-thread block ----------------
__global__ __launch_bounds__(TPB, 2)
void fused_main(const float* __restrict__ values,
                const float* __restrict__ gamma,
                const float* __restrict__ beta,
                float* __restrict__ out) {
    extern __shared__ __align__(16) char dynsm[];

    const int tid    = threadIdx.x;
    const int g      = tid >> 7;          // group 0..3
    const int wg_tid = tid & 127;         // tid within group
    const int lane   = tid & 31;
    const int warp   = (tid >> 5) & 3;    // warp within group
    const int b      = blockIdx.x * GROUPS + g;
    const int t0     = wg_tid << 3;

    float* sh_hs    = (float*)(dynsm + OFF_HS);                       // shared by all groups
    float* sh_x     = (float*)(dynsm + OFF_X)  + g * (S_N * D_N);
    float* sh_vp    = (float*)(dynsm + OFF_VP) + g * (S_N * VSA_N);
    char*  auxp     = dynsm + OFF_AUX + g * AUX_STRIDE;
    float* sh_red   = (float*)auxp;            // 8 floats
    float* sh_stats = (float*)(auxp + 32);     // 2 floats
    int*   sh_negw  = (int*)(auxp + 40);       // 100 ints
    float* sh_w     = (float*)(auxp + 440);    // 25 floats

    // cooperative loads (all 512 threads)
    {
        const float4* src = reinterpret_cast<const float4*>(g_hs);
        float4* dst = reinterpret_cast<float4*>(sh_hs);
        #pragma unroll 1
        for (int idx = tid; idx < (S_N * KTOT) / 4; idx += TPB) dst[idx] = src[idx];
    }
    {
        float* xall = (float*)(dynsm + OFF_X);
        const float* vb = values + (size_t)blockIdx.x * GROUPS * (S_N * D_N);
        #pragma unroll 1
        for (int idx = tid; idx < GROUPS * S_N * D_N; idx += TPB) xall[idx] = vb[idx];
    }
    __syncthreads();   // only block-wide barrier; groups independent after this

    // ---- conv + silu + LayerNorm per i -> sh_vp  [R2 logic, group barriers] ----
    #pragma unroll 1
    for (int i = 0; i < S_N; ++i) {
        float acc[8];
        conv_row2(sh_hs + i * KTOT, sh_x + i * D_N, t0, acc);

        float y[8];
        float s1 = 0.f, s2 = 0.f;
        #pragma unroll
        for (int r = 0; r < 8; ++r) {
            float u = fast_silu(acc[r]);
            y[r] = u; s1 += u; s2 += u * u;
        }
        #pragma unroll
        for (int o = 16; o > 0; o >>= 1) {
            s1 += __shfl_xor_sync(0xffffffffu, s1, o);
            s2 += __shfl_xor_sync(0xffffffffu, s2, o);
        }
        if (lane == 0) { sh_red[warp] = s1; sh_red[4 + warp] = s2; }
        GBAR();
        if (wg_tid == 0) {
            float a = sh_red[0] + sh_red[1] + sh_red[2] + sh_red[3];
            float q = sh_red[4] + sh_red[5] + sh_red[6] + sh_red[7];
            float mu = a * (1.f / VSA_N);
            float var = q * (1.f / VSA_N) - mu * mu;
            sh_stats[0] = mu;
            sh_stats[1] = rsqrtf(var + LN_EPSF);
        }
        GBAR();
        float mu = sh_stats[0], rs = sh_stats[1];

        float4 g0  = *reinterpret_cast<const float4*>(gamma + t0);
        float4 g1  = *reinterpret_cast<const float4*>(gamma + t0 + 4);
        float4 be0 = *reinterpret_cast<const float4*>(beta + t0);
        float4 be1 = *reinterpret_cast<const float4*>(beta + t0 + 4);
        float gg[8] = {g0.x, g0.y, g0.z, g0.w, g1.x, g1.y, g1.z, g1.w};
        float bb[8] = {be0.x, be0.y, be0.z, be0.w, be1.x, be1.y, be1.z, be1.w};
        float vv[8];
        #pragma unroll
        for (int r = 0; r < 8; ++r) vv[r] = fmaf((y[r] - mu) * rs, gg[r], bb[r]);
        *reinterpret_cast<float4*>(&sh_vp[i * VSA_N + t0])     = make_float4(vv[0], vv[1], vv[2], vv[3]);
        *reinterpret_cast<float4*>(&sh_vp[i * VSA_N + t0 + 4]) = make_float4(vv[4], vv[5], vv[6], vv[7]);
    }
    GBAR();   // all vp rows of this group visible

    // ---- scores: neg-count via sign-bit XOR (strided t = wg_tid + 128*r)  [R2 proven] ----
    int neg[25];
    #pragma unroll
    for (int q = 0; q < 25; ++q) neg[q] = 0;
    #pragma unroll 1
    for (int r = 0; r < 8; ++r) {
        const int t = wg_tid + (r << 7);
        float vpv[5]; int vpb[5]; float spv[5];
        #pragma unroll
        for (int i = 0; i < 5; ++i) {
            vpv[i] = sh_vp[i * VSA_N + t];
            vpb[i] = __float_as_int(vpv[i]);
        }
        #pragma unroll
        for (int j = 0; j < 5; ++j) spv[j] = g_sp[j * VSA_N + t];
        #pragma unroll
        for (int j = 0; j < 5; ++j) {
            #pragma unroll
            for (int i = 0; i < 5; ++i) {
                float c = vpv[i] + spv[j];
                neg[j * 5 + i] += (int)(((unsigned)(vpb[i] ^ __float_as_int(c))) >> 31);
            }
        }
    }
    #pragma unroll
    for (int q = 0; q < 25; ++q) neg[q] = __reduce_add_sync(0xffffffffu, neg[q]);
    if (lane == 0) {
        #pragma unroll
        for (int q = 0; q < 25; ++q) sh_negw[warp * 25 + q] = neg[q];
    }
    GBAR();
    if (wg_tid < 25) {
        int tot = sh_negw[wg_tid] + sh_negw[25 + wg_tid] + sh_negw[50 + wg_tid] + sh_negw[75 + wg_tid];
        sh_w[wg_tid] = (float)(VSA_N - 2 * tot) * (1.f / VSA_N);
    }
    GBAR();
    if (wg_tid < 5) {   // softmax over i for row j = wg_tid
        float s[5];
        #pragma unroll
        for (int i = 0; i < 5; ++i) s[i] = sh_w[wg_tid * 5 + i];
        float m = s[0];
        #pragma unroll
        for (int i = 1; i < 5; ++i) m = fmaxf(m, s[i]);
        float e[5]; float sum = 0.f;
        #pragma unroll
        for (int i = 0; i < 5; ++i) { e[i] = __expf(s[i] - m); sum += e[i]; }
        float inv = 1.f / sum;
        #pragma unroll
        for (int i = 0; i < 5; ++i) sh_w[wg_tid * 5 + i] = e[i] * inv;
    }
    GBAR();

    // ---- att + final silu + store (strided t, coalesced)  [R2 proven] ----
    float wloc[25];
    #pragma unroll
    for (int q = 0; q < 25; ++q) wloc[q] = sh_w[q];
    const int ob = b * (S_N * VSA_N);
    #pragma unroll 1
    for (int r = 0; r < 8; ++r) {
        const int t = wg_tid + (r << 7);
        float vpv[5], spv[5];
        #pragma unroll
        for (int i = 0; i < 5; ++i) vpv[i] = sh_vp[i * VSA_N + t];
        #pragma unroll
        for (int j = 0; j < 5; ++j) spv[j] = g_sp[j * VSA_N + t];
        #pragma unroll
        for (int j = 0; j < 5; ++j) {
            float a = 0.f;
            #pragma unroll
            for (int i = 0; i < 5; ++i) a = fmaf(wloc[j * 5 + i], vpv[i], a);
            out[ob + j * VSA_N + t] = fast_silu(a * spv[j]);
        }
    }
}

extern "C" void kernel_launch(void* const* d_in, const int* in_sizes, int n_in,
                              void* d_out, int out_size) {
    (void)in_sizes; (void)n_in; (void)out_size;
    const float* values  = (const float*)d_in[0];
    const float* h       = (const float*)d_in[1];
    const float* symbols = (const float*)d_in[2];
    const float* gamma   = (const float*)d_in[3];
    const float* beta    = (const float*)d_in[4];
    float* out = (float*)d_out;

    static int attr_set = 0;
    if (!attr_set) {
        cudaFuncSetAttribute(fused_main, cudaFuncAttributeMaxDynamicSharedMemorySize, SMEM_DYN);
        attr_set = 1;
    }

    sp_kernel<<<S_N, 128>>>(h, symbols, gamma, beta);
    fused_main<<<B_N / GROUPS, TPB, SMEM_DYN>>>(values, gamma, beta, out);
}